// round 15
// baseline (speedup 1.0000x reference)
#include <cuda_runtime.h>
#include <math.h>

#define BB 32
#define SS 2048
#define HH 1024
#define UU 128
#define H4 (HH / 4)        // 256 float4 per row
#define KC 8               // split-K for k_v
#define WPB 8              // warps per attn block
#define NBLK 296           // attn blocks = 148 SMs x 2 (exact wave)
#define NCH 74             // chunks per batch (NBLK*WPB / BB = 74 exactly)
#define CBASE 27           // base rows per chunk
#define CREM 50            // first CREM chunks get CBASE+1 = 28 rows
#define RING 3             // per-warp smem ring depth (rows)
#define JC2 128            // j-chunks for output GEMM
#define JCW (2 * HH / JC2) // 16 j-rows per chunk
#define BG 8               // batch groups for output GEMM (4 batches each)

// ---- device scratch (no runtime allocation allowed) ----
__device__ float g_vp[KC * BB * HH];                // split-K partials of v = W @ h_t
__device__ float g_pm[BB * NCH];                    // per-chunk running max
__device__ float g_pl[BB * NCH];                    // per-chunk denom
__device__ float g_pacc[(size_t)BB * NCH * HH];     // per-chunk unnormalized context (~9.7 MB)
__device__ float g_pre[BB * 2 * HH];                // [context ; h_t]
__device__ float g_pout[JC2 * BB * UU];             // split-K partials of final GEMM (2 MB)

__device__ __forceinline__ void cp_async16(void* smem, const void* gmem) {
    unsigned saddr = (unsigned)__cvta_generic_to_shared(smem);
    asm volatile("cp.async.cg.shared.global [%0], [%1], 16;\n" :: "r"(saddr), "l"(gmem));
}
__device__ __forceinline__ void cp_commit() {
    asm volatile("cp.async.commit_group;\n" ::: "memory");
}
template <int N>
__device__ __forceinline__ void cp_wait() {
    asm volatile("cp.async.wait_group %0;\n" :: "n"(N) : "memory");
}

// ============================================================
// K1: split-K partial of v[b,h] = dot(w_score[h,:], h_t[b,:]).
// Grid (64 h-chunks, 8 k-chunks) = 512 blocks. One-shot tiles, 1 barrier.
// ============================================================
__global__ void __launch_bounds__(256) k_v(const float* __restrict__ hidden,
                                           const float* __restrict__ wsc) {
    __shared__ float sht[32][132];   // 32 b x 128 k (+4 pad)
    __shared__ float swt[16][132];   // 16 h x 128 k (+4 pad)
    const int t = threadIdx.x;              // 256 threads
    const int h0 = blockIdx.x * 16;         // 64 h-chunks
    const int kb4 = blockIdx.y * 32;        // k-chunk base in float4 units

    const float4* __restrict__ hid4 = reinterpret_cast<const float4*>(hidden);
    const float4* __restrict__ wsc4 = reinterpret_cast<const float4*>(wsc);

    #pragma unroll
    for (int i = 0; i < 4; i++) {
        int fi = t + i * 256;
        int b = fi >> 5, k4 = fi & 31;
        float4 v = hid4[((size_t)b * SS + (SS - 1)) * H4 + kb4 + k4];
        *reinterpret_cast<float4*>(&sht[b][k4 * 4]) = v;
    }
    #pragma unroll
    for (int i = 0; i < 2; i++) {
        int fi = t + i * 256;
        int h = fi >> 5, k4 = fi & 31;
        float4 v = wsc4[(size_t)(h0 + h) * H4 + kb4 + k4];
        *reinterpret_cast<float4*>(&swt[h][k4 * 4]) = v;
    }
    __syncthreads();

    #pragma unroll
    for (int j = 0; j < 2; j++) {
        int o = t + j * 256;
        int b = o >> 4, h = o & 15;
        float a = 0.f;
        #pragma unroll 8
        for (int k = 0; k < 128; k++) a += swt[h][k] * sht[b][k];
        g_vp[((size_t)blockIdx.y * BB + b) * HH + h0 + h] = a;
    }
}

// ============================================================
// K2: barrier-free per-warp pipelined flash attention, EXACT-WAVE grid.
// 296 blocks x 8 warps = 2368 warps = 32 batches x 74 chunks.
// Chunk j of a batch: 28 rows for j<50, else 27 (|delta| <= 1 row).
// Warp w owns its chunk; lane l owns H-slots {k*32+l}; per-warp 3-row
// smem ring; no block/warp barriers in the loop.
// ============================================================
__global__ void __launch_bounds__(256, 2) k_attn(const float* __restrict__ hidden) {
    extern __shared__ float4 ring[];          // [WPB][RING][H4] = 96 KB

    const int t = threadIdx.x;     // 256
    const int w = t >> 5;
    const int l = t & 31;
    const int gw = blockIdx.x * WPB + w;      // 0..2367
    const int b = gw / NCH;
    const int j = gw - b * NCH;               // chunk 0..73
    const int rows = (j < CREM) ? (CBASE + 1) : CBASE;
    const int s0 = (j < CREM) ? j * (CBASE + 1) : CBASE * j + CREM;

    float4* __restrict__ myring = ring + (size_t)w * RING * H4;
    const float4* __restrict__ hid = reinterpret_cast<const float4*>(hidden) + (size_t)b * SS * H4;
    const float4* __restrict__ vp4 = reinterpret_cast<const float4*>(g_vp);

    // v[b]: 8 float4/lane, summed over KC split-K partials (L2-resident)
    float4 vv[8];
    #pragma unroll
    for (int k = 0; k < 8; k++) vv[k] = make_float4(0.f, 0.f, 0.f, 0.f);
    #pragma unroll
    for (int p = 0; p < KC; p++) {
        #pragma unroll
        for (int k = 0; k < 8; k++) {
            const float4 a = vp4[((size_t)p * BB + b) * H4 + k * 32 + l];
            vv[k].x += a.x; vv[k].y += a.y; vv[k].z += a.z; vv[k].w += a.w;
        }
    }

    // prologue: rows 0,1 in flight (one commit group per row)
    #pragma unroll
    for (int pre = 0; pre < 2; pre++) {
        #pragma unroll
        for (int k = 0; k < 8; k++)
            cp_async16(&myring[pre * H4 + k * 32 + l],
                       &hid[(size_t)(s0 + pre) * H4 + k * 32 + l]);
        cp_commit();
    }

    float4 acc[8];
    #pragma unroll
    for (int k = 0; k < 8; k++) acc[k] = make_float4(0.f, 0.f, 0.f, 0.f);
    float m = -INFINITY, L = 0.f;

    for (int i = 0; i < rows; i++) {
        // issue row i+2 into the slot row i-1 vacated (lane-owned addresses)
        if (i + 2 < rows) {
            float4* nb = &myring[((i + 2) % RING) * H4];
            #pragma unroll
            for (int k = 0; k < 8; k++)
                cp_async16(&nb[k * 32 + l], &hid[(size_t)(s0 + i + 2) * H4 + k * 32 + l]);
        }
        cp_commit();            // one group per iteration (empty at tail)
        cp_wait<2>();           // row i complete; rows i+1, i+2 in flight

        const float4* rb = &myring[(i % RING) * H4];
        float4 hv[8];
        #pragma unroll
        for (int k = 0; k < 8; k++) hv[k] = rb[k * 32 + l];

        // score: lane-local partial dot + 5-shuffle warp reduce
        float p = 0.f;
        #pragma unroll
        for (int k = 0; k < 8; k++)
            p += hv[k].x * vv[k].x + hv[k].y * vv[k].y + hv[k].z * vv[k].z + hv[k].w * vv[k].w;
        #pragma unroll
        for (int o = 16; o > 0; o >>= 1) p += __shfl_xor_sync(0xffffffffu, p, o);

        // online softmax (per-warp state, registers only)
        const float mn = fmaxf(m, p);
        const float sc = __expf(m - mn);     // 0 on first row
        const float pp = __expf(p - mn);
        L = L * sc + pp;
        #pragma unroll
        for (int k = 0; k < 8; k++) {
            acc[k].x = acc[k].x * sc + pp * hv[k].x;
            acc[k].y = acc[k].y * sc + pp * hv[k].y;
            acc[k].z = acc[k].z * sc + pp * hv[k].z;
            acc[k].w = acc[k].w * sc + pp * hv[k].w;
        }
        m = mn;
    }

    if (l == 0) { g_pm[b * NCH + j] = m; g_pl[b * NCH + j] = L; }
    float4* pacc4 = reinterpret_cast<float4*>(g_pacc);
    #pragma unroll
    for (int k = 0; k < 8; k++)
        pacc4[((size_t)b * NCH + j) * H4 + k * 32 + l] = acc[k];
}

// ============================================================
// K3: merge 74 chunk partials -> context; build pre = [context ; h_t].
// Grid (B, 4) x 256: warp 0 computes weights (strided); group cg
// accumulates chunks c = cg, cg+4, ... ; smem reduce over cg.
// ============================================================
__global__ void __launch_bounds__(256) k_combine(const float* __restrict__ hidden) {
    const int b = blockIdx.x;
    const int t = threadIdx.x;      // 256
    const int cg = t >> 6;          // 0..3
    const int hl = t & 63;
    __shared__ float sm[NCH], sl[NCH], wgt[NCH];
    __shared__ float sinv;
    __shared__ float4 red[4][64];

    if (t < NCH) { sm[t] = g_pm[b * NCH + t]; sl[t] = g_pl[b * NCH + t]; }
    __syncthreads();

    if (t < 32) {
        float M = -INFINITY;
        for (int c = t; c < NCH; c += 32) M = fmaxf(M, sm[c]);
        #pragma unroll
        for (int o = 16; o > 0; o >>= 1) M = fmaxf(M, __shfl_xor_sync(0xffffffffu, M, o));
        float Lp = 0.f;
        for (int c = t; c < NCH; c += 32) {
            const float e = __expf(sm[c] - M);
            wgt[c] = e;
            Lp += sl[c] * e;
        }
        #pragma unroll
        for (int o = 16; o > 0; o >>= 1) Lp += __shfl_xor_sync(0xffffffffu, Lp, o);
        if (t == 0) sinv = 1.f / Lp;
    }
    __syncthreads();

    const int hi = blockIdx.y * 64 + hl;   // float4 index within H4
    const float4* pacc4 = reinterpret_cast<const float4*>(g_pacc);

    float4 ctx = make_float4(0.f, 0.f, 0.f, 0.f);
    for (int c = cg; c < NCH; c += 4) {
        const float e = wgt[c];
        const float4 a = pacc4[((size_t)b * NCH + c) * H4 + hi];
        ctx.x += e * a.x; ctx.y += e * a.y; ctx.z += e * a.z; ctx.w += e * a.w;
    }
    red[cg][hl] = ctx;
    __syncthreads();

    if (cg == 0) {
        const float inv = sinv;
        float4 s = red[0][hl], a1 = red[1][hl], a2 = red[2][hl], a3 = red[3][hl];
        s.x = (s.x + a1.x + a2.x + a3.x) * inv;
        s.y = (s.y + a1.y + a2.y + a3.y) * inv;
        s.z = (s.z + a1.z + a2.z + a3.z) * inv;
        s.w = (s.w + a1.w + a2.w + a3.w) * inv;
        float4* pre4 = reinterpret_cast<float4*>(g_pre);
        pre4[b * (2 * H4) + hi] = s;
        pre4[b * (2 * H4) + H4 + hi] =
            reinterpret_cast<const float4*>(hidden)[((size_t)b * SS + (SS - 1)) * H4 + hi];
    }
}

// ============================================================
// K4: split-K output GEMM, (128 j-chunks x 8 batch-groups) = 1024 blocks.
// Thread (brel, u4): float4 of U for 4 batches; wout read as float4.
// ============================================================
__global__ void __launch_bounds__(128) k_outp(const float* __restrict__ wout) {
    const int p = blockIdx.x;     // 128
    const int bg = blockIdx.y;    // 8
    const int t = threadIdx.x;    // 128
    const int u4 = t & 31;
    const int brel = t >> 5;      // 0..3
    const int j0 = p * JCW;
    const int b0 = bg * 4;

    __shared__ float spre[4][JCW];   // 256B
    if (t < 64) spre[t >> 4][t & 15] = g_pre[(b0 + (t >> 4)) * (2 * HH) + j0 + (t & 15)];
    __syncthreads();

    const float4* __restrict__ wo4 = reinterpret_cast<const float4*>(wout);
    float4 acc = make_float4(0.f, 0.f, 0.f, 0.f);
    const float* myp = spre[brel];

    #pragma unroll
    for (int jj = 0; jj < JCW; jj++) {
        const float4 wv = wo4[(size_t)(j0 + jj) * 32 + u4];
        const float pr = myp[jj];
        acc.x += pr * wv.x; acc.y += pr * wv.y; acc.z += pr * wv.z; acc.w += pr * wv.w;
    }
    reinterpret_cast<float4*>(g_pout)[((size_t)p * BB + b0 + brel) * 32 + u4] = acc;
}

// K5: reduce 128 partials (8-way split + smem reduce) + tanh -> output
__global__ void __launch_bounds__(256) k_outf(float* __restrict__ out) {
    const int b = blockIdx.x;   // 32 blocks
    const int t = threadIdx.x;  // 256
    const int u4 = t & 31;
    const int pg = t >> 5;      // 0..7
    __shared__ float4 red[8][32];

    const float4* __restrict__ po4 = reinterpret_cast<const float4*>(g_pout);
    float4 a = make_float4(0.f, 0.f, 0.f, 0.f);
    #pragma unroll
    for (int pp = 0; pp < 16; pp++) {
        const int p = pg * 16 + pp;
        const float4 v = po4[((size_t)p * BB + b) * 32 + u4];
        a.x += v.x; a.y += v.y; a.z += v.z; a.w += v.w;
    }
    red[pg][u4] = a;
    __syncthreads();

    if (pg == 0) {
        float4 s = red[0][u4];
        #pragma unroll
        for (int g = 1; g < 8; g++) {
            const float4 v = red[g][u4];
            s.x += v.x; s.y += v.y; s.z += v.z; s.w += v.w;
        }
        s.x = tanhf(s.x); s.y = tanhf(s.y); s.z = tanhf(s.z); s.w = tanhf(s.w);
        reinterpret_cast<float4*>(out)[b * 32 + u4] = s;
    }
}

extern "C" void kernel_launch(void* const* d_in, const int* in_sizes, int n_in,
                              void* d_out, int out_size) {
    const float* hidden = (const float*)d_in[0];  // (32, 2048, 1024) f32
    const float* wsc    = (const float*)d_in[1];  // (1024, 1024) f32
    const float* wout   = (const float*)d_in[2];  // (2048, 128) f32
    float* out = (float*)d_out;                   // (32, 128) f32

    const int attn_smem = WPB * RING * H4 * (int)sizeof(float4);  // 96 KB
    cudaFuncSetAttribute(k_attn, cudaFuncAttributeMaxDynamicSharedMemorySize, attn_smem);

    k_v<<<dim3(64, KC), 256>>>(hidden, wsc);
    k_attn<<<NBLK, 256, attn_smem>>>(hidden);
    k_combine<<<dim3(BB, 4), 256>>>(hidden);
    k_outp<<<dim3(JC2, BG), 128>>>(wout);
    k_outf<<<BB, 256>>>(out);
}

// round 16
// speedup vs baseline: 1.0477x; 1.0477x over previous
#include <cuda_runtime.h>
#include <math.h>

#define BB 32
#define SS 2048
#define HH 1024
#define UU 128
#define H4 (HH / 4)        // 256 float4 per row
#define KC 8               // split-K for k_v
#define CBLK 8             // attn blocks per batch
#define WPB 8              // warps per attn block
#define NCH (CBLK * WPB)   // 64 chunks per batch (one per warp)
#define RW (SS / NCH)      // 32 rows per warp
#define RING 3             // per-warp smem ring depth (rows)
#define JC2 128            // j-chunks for output GEMM
#define JCW (2 * HH / JC2) // 16 j-rows per chunk
#define BG 8               // batch groups for output GEMM (4 batches each)

// ---- device scratch (no runtime allocation allowed) ----
__device__ float g_vp[KC * BB * HH];                // split-K partials of v = W @ h_t
__device__ float g_pm[BB * NCH];                    // per-chunk running max
__device__ float g_pl[BB * NCH];                    // per-chunk denom
__device__ float g_pacc[(size_t)BB * NCH * HH];     // per-chunk unnormalized context (8 MB)
__device__ float g_pre[BB * 2 * HH];                // [context ; h_t]
__device__ float g_pout[JC2 * BB * UU];             // split-K partials of final GEMM (2 MB)

__device__ __forceinline__ void cp_async16(void* smem, const void* gmem) {
    unsigned saddr = (unsigned)__cvta_generic_to_shared(smem);
    asm volatile("cp.async.cg.shared.global [%0], [%1], 16;\n" :: "r"(saddr), "l"(gmem));
}
__device__ __forceinline__ void cp_commit() {
    asm volatile("cp.async.commit_group;\n" ::: "memory");
}
template <int N>
__device__ __forceinline__ void cp_wait() {
    asm volatile("cp.async.wait_group %0;\n" :: "n"(N) : "memory");
}

// ---- packed f32x2 math (Blackwell FFMA2 — PTX-only path) ----
union F2U { float2 f; unsigned long long u; };

__device__ __forceinline__ unsigned long long fma2(unsigned long long a,
                                                   unsigned long long b,
                                                   unsigned long long c) {
    unsigned long long d;
    asm("fma.rn.f32x2 %0, %1, %2, %3;" : "=l"(d) : "l"(a), "l"(b), "l"(c));
    return d;
}
__device__ __forceinline__ unsigned long long mul2p(unsigned long long a,
                                                    unsigned long long b) {
    unsigned long long d;
    asm("mul.rn.f32x2 %0, %1, %2;" : "=l"(d) : "l"(a), "l"(b));
    return d;
}

// ============================================================
// K1: split-K partial of v[b,h] = dot(w_score[h,:], h_t[b,:]).
// Grid (64 h-chunks, 8 k-chunks) = 512 blocks. One-shot tiles, 1 barrier.
// ============================================================
__global__ void __launch_bounds__(256) k_v(const float* __restrict__ hidden,
                                           const float* __restrict__ wsc) {
    __shared__ float sht[32][132];   // 32 b x 128 k (+4 pad)
    __shared__ float swt[16][132];   // 16 h x 128 k (+4 pad)
    const int t = threadIdx.x;              // 256 threads
    const int h0 = blockIdx.x * 16;         // 64 h-chunks
    const int kb4 = blockIdx.y * 32;        // k-chunk base in float4 units

    const float4* __restrict__ hid4 = reinterpret_cast<const float4*>(hidden);
    const float4* __restrict__ wsc4 = reinterpret_cast<const float4*>(wsc);

    #pragma unroll
    for (int i = 0; i < 4; i++) {
        int fi = t + i * 256;
        int b = fi >> 5, k4 = fi & 31;
        float4 v = hid4[((size_t)b * SS + (SS - 1)) * H4 + kb4 + k4];
        *reinterpret_cast<float4*>(&sht[b][k4 * 4]) = v;
    }
    #pragma unroll
    for (int i = 0; i < 2; i++) {
        int fi = t + i * 256;
        int h = fi >> 5, k4 = fi & 31;
        float4 v = wsc4[(size_t)(h0 + h) * H4 + kb4 + k4];
        *reinterpret_cast<float4*>(&swt[h][k4 * 4]) = v;
    }
    __syncthreads();

    #pragma unroll
    for (int j = 0; j < 2; j++) {
        int o = t + j * 256;
        int b = o >> 4, h = o & 15;
        float a = 0.f;
        #pragma unroll 8
        for (int k = 0; k < 128; k++) a += swt[h][k] * sht[b][k];
        g_vp[((size_t)blockIdx.y * BB + b) * HH + h0 + h] = a;
    }
}

// ============================================================
// K2: barrier-free per-warp pipelined flash attention with packed
// f32x2 math and deferred (max-change-only) rescaling.
// Warp w owns 32 contiguous rows; lane l owns H-slots {k*32+l};
// per-warp 3-row smem ring; no block/warp barriers in the loop.
// ============================================================
__global__ void __launch_bounds__(256, 2) k_attn(const float* __restrict__ hidden) {
    extern __shared__ float4 ring[];          // [WPB][RING][H4] = 96 KB

    const int b = blockIdx.y;
    const int t = threadIdx.x;     // 256
    const int w = t >> 5;
    const int l = t & 31;
    const int c = blockIdx.x * WPB + w;       // chunk 0..63
    const int s0 = c * RW;

    float4* __restrict__ myring = ring + (size_t)w * RING * H4;
    const float4* __restrict__ hid = reinterpret_cast<const float4*>(hidden) + (size_t)b * SS * H4;
    const float4* __restrict__ vp4 = reinterpret_cast<const float4*>(g_vp);

    // v[b]: 8 float4/lane, summed over KC split-K partials, packed as 16 f32x2
    unsigned long long vv2[16];
    {
        float4 vv[8];
        #pragma unroll
        for (int k = 0; k < 8; k++) vv[k] = make_float4(0.f, 0.f, 0.f, 0.f);
        #pragma unroll
        for (int p = 0; p < KC; p++) {
            #pragma unroll
            for (int k = 0; k < 8; k++) {
                const float4 a = vp4[((size_t)p * BB + b) * H4 + k * 32 + l];
                vv[k].x += a.x; vv[k].y += a.y; vv[k].z += a.z; vv[k].w += a.w;
            }
        }
        #pragma unroll
        for (int k = 0; k < 8; k++) {
            F2U lo, hi;
            lo.f = make_float2(vv[k].x, vv[k].y);
            hi.f = make_float2(vv[k].z, vv[k].w);
            vv2[2 * k] = lo.u;
            vv2[2 * k + 1] = hi.u;
        }
    }

    // prologue: rows 0,1 in flight (one commit group per row)
    #pragma unroll
    for (int pre = 0; pre < 2; pre++) {
        #pragma unroll
        for (int k = 0; k < 8; k++)
            cp_async16(&myring[pre * H4 + k * 32 + l],
                       &hid[(size_t)(s0 + pre) * H4 + k * 32 + l]);
        cp_commit();
    }

    unsigned long long accp[16];
    #pragma unroll
    for (int k = 0; k < 16; k++) accp[k] = 0ull;     // (0.0f, 0.0f)
    float m = -INFINITY, L = 0.f;

    for (int i = 0; i < RW; i++) {
        // issue row i+2 into the slot row i-1 vacated (lane-owned addresses)
        if (i + 2 < RW) {
            float4* nb = &myring[((i + 2) % RING) * H4];
            #pragma unroll
            for (int k = 0; k < 8; k++)
                cp_async16(&nb[k * 32 + l], &hid[(size_t)(s0 + i + 2) * H4 + k * 32 + l]);
        }
        cp_commit();            // one group per iteration (empty at tail)
        cp_wait<2>();           // row i complete; rows i+1, i+2 in flight

        const ulonglong2* rb2 =
            reinterpret_cast<const ulonglong2*>(&myring[(i % RING) * H4]);
        unsigned long long hv2[16];
        #pragma unroll
        for (int k = 0; k < 8; k++) {
            const ulonglong2 d = rb2[k * 32 + l];
            hv2[2 * k] = d.x;
            hv2[2 * k + 1] = d.y;
        }

        // score: two independent packed-FFMA chains + 5-shuffle warp reduce
        unsigned long long ps0 = 0ull, ps1 = 0ull;
        #pragma unroll
        for (int k = 0; k < 8; k++) {
            ps0 = fma2(hv2[2 * k], vv2[2 * k], ps0);
            ps1 = fma2(hv2[2 * k + 1], vv2[2 * k + 1], ps1);
        }
        F2U u0, u1; u0.u = ps0; u1.u = ps1;
        float p = (u0.f.x + u0.f.y) + (u1.f.x + u1.f.y);
        #pragma unroll
        for (int o = 16; o > 0; o >>= 1) p += __shfl_xor_sync(0xffffffffu, p, o);

        // deferred-rescale online softmax (warp-uniform branch, ~ln(32) hits)
        if (p > m) {
            const float rs = __expf(m - p);    // 0 on first row (m = -inf)
            F2U r2; r2.f = make_float2(rs, rs);
            L *= rs;
            #pragma unroll
            for (int k = 0; k < 16; k++) accp[k] = mul2p(accp[k], r2.u);
            m = p;
        }
        const float pp = __expf(p - m);
        F2U pw; pw.f = make_float2(pp, pp);
        L += pp;
        #pragma unroll
        for (int k = 0; k < 16; k++) accp[k] = fma2(hv2[k], pw.u, accp[k]);
    }

    if (l == 0) { g_pm[b * NCH + c] = m; g_pl[b * NCH + c] = L; }
    float4* pacc4 = reinterpret_cast<float4*>(g_pacc);
    #pragma unroll
    for (int k = 0; k < 8; k++) {
        F2U lo, hi; lo.u = accp[2 * k]; hi.u = accp[2 * k + 1];
        pacc4[((size_t)b * NCH + c) * H4 + k * 32 + l] =
            make_float4(lo.f.x, lo.f.y, hi.f.x, hi.f.y);
    }
}

// ============================================================
// K3: merge 64 chunk partials -> context; build pre = [context ; h_t].
// Grid (B, 4) x 256: group cg sums 16 chunks; smem reduce over cg.
// ============================================================
__global__ void __launch_bounds__(256) k_combine(const float* __restrict__ hidden) {
    const int b = blockIdx.x;
    const int t = threadIdx.x;      // 256
    const int cg = t >> 6;          // 0..3
    const int hl = t & 63;
    __shared__ float sm[NCH], sl[NCH], wgt[NCH];
    __shared__ float sinv;
    __shared__ float4 red[4][64];

    if (t < NCH) { sm[t] = g_pm[b * NCH + t]; sl[t] = g_pl[b * NCH + t]; }
    __syncthreads();

    if (t < 32) {
        float M = fmaxf(sm[t], sm[t + 32]);
        #pragma unroll
        for (int o = 16; o > 0; o >>= 1) M = fmaxf(M, __shfl_xor_sync(0xffffffffu, M, o));
        float e0 = __expf(sm[t] - M), e1 = __expf(sm[t + 32] - M);
        wgt[t] = e0; wgt[t + 32] = e1;
        float Lp = sl[t] * e0 + sl[t + 32] * e1;
        #pragma unroll
        for (int o = 16; o > 0; o >>= 1) Lp += __shfl_xor_sync(0xffffffffu, Lp, o);
        if (t == 0) sinv = 1.f / Lp;
    }
    __syncthreads();

    const int hi = blockIdx.y * 64 + hl;   // float4 index within H4
    const float4* pacc4 = reinterpret_cast<const float4*>(g_pacc);

    float4 ctx = make_float4(0.f, 0.f, 0.f, 0.f);
    #pragma unroll
    for (int cc = 0; cc < 16; cc++) {
        const int c = cg * 16 + cc;
        const float e = wgt[c];
        const float4 a = pacc4[((size_t)b * NCH + c) * H4 + hi];
        ctx.x += e * a.x; ctx.y += e * a.y; ctx.z += e * a.z; ctx.w += e * a.w;
    }
    red[cg][hl] = ctx;
    __syncthreads();

    if (cg == 0) {
        const float inv = sinv;
        float4 s = red[0][hl], a1 = red[1][hl], a2 = red[2][hl], a3 = red[3][hl];
        s.x = (s.x + a1.x + a2.x + a3.x) * inv;
        s.y = (s.y + a1.y + a2.y + a3.y) * inv;
        s.z = (s.z + a1.z + a2.z + a3.z) * inv;
        s.w = (s.w + a1.w + a2.w + a3.w) * inv;
        float4* pre4 = reinterpret_cast<float4*>(g_pre);
        pre4[b * (2 * H4) + hi] = s;
        pre4[b * (2 * H4) + H4 + hi] =
            reinterpret_cast<const float4*>(hidden)[((size_t)b * SS + (SS - 1)) * H4 + hi];
    }
}

// ============================================================
// K4: split-K output GEMM, (128 j-chunks x 8 batch-groups) = 1024 blocks.
// Thread (brel, u4): float4 of U for 4 batches; wout read as float4.
// ============================================================
__global__ void __launch_bounds__(128) k_outp(const float* __restrict__ wout) {
    const int p = blockIdx.x;     // 128
    const int bg = blockIdx.y;    // 8
    const int t = threadIdx.x;    // 128
    const int u4 = t & 31;
    const int brel = t >> 5;      // 0..3
    const int j0 = p * JCW;
    const int b0 = bg * 4;

    __shared__ float spre[4][JCW];   // 256B
    if (t < 64) spre[t >> 4][t & 15] = g_pre[(b0 + (t >> 4)) * (2 * HH) + j0 + (t & 15)];
    __syncthreads();

    const float4* __restrict__ wo4 = reinterpret_cast<const float4*>(wout);
    float4 acc = make_float4(0.f, 0.f, 0.f, 0.f);
    const float* myp = spre[brel];

    #pragma unroll
    for (int jj = 0; jj < JCW; jj++) {
        const float4 wv = wo4[(size_t)(j0 + jj) * 32 + u4];
        const float pr = myp[jj];
        acc.x += pr * wv.x; acc.y += pr * wv.y; acc.z += pr * wv.z; acc.w += pr * wv.w;
    }
    reinterpret_cast<float4*>(g_pout)[((size_t)p * BB + b0 + brel) * 32 + u4] = acc;
}

// K5: reduce 128 partials (8-way split + smem reduce) + tanh -> output
__global__ void __launch_bounds__(256) k_outf(float* __restrict__ out) {
    const int b = blockIdx.x;   // 32 blocks
    const int t = threadIdx.x;  // 256
    const int u4 = t & 31;
    const int pg = t >> 5;      // 0..7
    __shared__ float4 red[8][32];

    const float4* __restrict__ po4 = reinterpret_cast<const float4*>(g_pout);
    float4 a = make_float4(0.f, 0.f, 0.f, 0.f);
    #pragma unroll
    for (int pp = 0; pp < 16; pp++) {
        const int p = pg * 16 + pp;
        const float4 v = po4[((size_t)p * BB + b) * 32 + u4];
        a.x += v.x; a.y += v.y; a.z += v.z; a.w += v.w;
    }
    red[pg][u4] = a;
    __syncthreads();

    if (pg == 0) {
        float4 s = red[0][u4];
        #pragma unroll
        for (int g = 1; g < 8; g++) {
            const float4 v = red[g][u4];
            s.x += v.x; s.y += v.y; s.z += v.z; s.w += v.w;
        }
        s.x = tanhf(s.x); s.y = tanhf(s.y); s.z = tanhf(s.z); s.w = tanhf(s.w);
        reinterpret_cast<float4*>(out)[b * 32 + u4] = s;
    }
}

extern "C" void kernel_launch(void* const* d_in, const int* in_sizes, int n_in,
                              void* d_out, int out_size) {
    const float* hidden = (const float*)d_in[0];  // (32, 2048, 1024) f32
    const float* wsc    = (const float*)d_in[1];  // (1024, 1024) f32
    const float* wout   = (const float*)d_in[2];  // (2048, 128) f32
    float* out = (float*)d_out;                   // (32, 128) f32

    const int attn_smem = WPB * RING * H4 * (int)sizeof(float4);  // 96 KB
    cudaFuncSetAttribute(k_attn, cudaFuncAttributeMaxDynamicSharedMemorySize, attn_smem);

    k_v<<<dim3(64, KC), 256>>>(hidden, wsc);
    k_attn<<<dim3(CBLK, BB), 256, attn_smem>>>(hidden);
    k_combine<<<dim3(BB, 4), 256>>>(hidden);
    k_outp<<<dim3(JC2, BG), 128>>>(wout);
    k_outf<<<BB, 256>>>(out);
}